// round 1
// baseline (speedup 1.0000x reference)
#include <cuda_runtime.h>
#include <math.h>

#define NN 50000
#define HH 4
#define CC 32
#define F1 128
#define F2 64
#define NEG 0.2f
#define EPSV 1e-16f

// ---------------- scratch (device globals; no allocations allowed) ----------
__device__ float g_xw1[NN * F1];     // x @ W1            [N,128]
__device__ float g_h1 [NN * F1];     // layer1 output     [N,128]
__device__ float g_asrc1[NN * HH];
__device__ float g_adst1[NN * HH];
__device__ float g_m1[NN * HH];
__device__ float g_s1[NN * HH];
__device__ float g_xw2[NN * F2];     // h @ W2            [N,64]
__device__ float g_asrc2[NN];
__device__ float g_adst2[NN];
__device__ float g_m2[NN];
__device__ float g_s2[NN];

__device__ __forceinline__ float lrelu(float v) { return v > 0.f ? v : NEG * v; }

// float atomic max via monotone int/uint encodings (deterministic)
__device__ __forceinline__ void atomicMaxF(float* addr, float v) {
    if (v >= 0.f) atomicMax((int*)addr, __float_as_int(v));
    else          atomicMin((unsigned int*)addr, __float_as_uint(v));
}

// ---------------- SGEMM: C[M,Ncols] = A[M,K] @ B[K,Ncols] -------------------
// BM=64, BN=64, BK=16, 256 threads, 4x4 microtile per thread.
__global__ __launch_bounds__(256) void gemm_kernel(
    const float* __restrict__ A, const float* __restrict__ B,
    float* __restrict__ C, int M, int Ncols, int K)
{
    const int BM = 64, BN = 64, BK = 16;
    __shared__ float As[BM][BK];
    __shared__ float Bs[BK][BN];

    int tid = threadIdx.x;
    int tx = tid & 15;          // 0..15 (col group)
    int ty = tid >> 4;          // 0..15 (row group)
    int row0 = blockIdx.y * BM;
    int col0 = blockIdx.x * BN;

    float acc[4][4] = {};

    for (int k0 = 0; k0 < K; k0 += BK) {
        // load A tile: 64x16 floats = 256 float4, one per thread
        {
            int r  = tid >> 2;            // 0..63
            int c4 = (tid & 3) * 4;       // 0,4,8,12
            int gr = row0 + r;
            float4 v = make_float4(0.f, 0.f, 0.f, 0.f);
            if (gr < M) v = *(const float4*)(A + (size_t)gr * K + k0 + c4);
            As[r][c4 + 0] = v.x; As[r][c4 + 1] = v.y;
            As[r][c4 + 2] = v.z; As[r][c4 + 3] = v.w;
        }
        // load B tile: 16x64 floats = 256 float4, one per thread
        {
            int r  = tid >> 4;            // 0..15
            int c4 = (tid & 15) * 4;      // 0..60
            float4 v = *(const float4*)(B + (size_t)(k0 + r) * Ncols + col0 + c4);
            Bs[r][c4 + 0] = v.x; Bs[r][c4 + 1] = v.y;
            Bs[r][c4 + 2] = v.z; Bs[r][c4 + 3] = v.w;
        }
        __syncthreads();

        #pragma unroll
        for (int kk = 0; kk < BK; kk++) {
            float a[4], b[4];
            #pragma unroll
            for (int i = 0; i < 4; i++) a[i] = As[ty * 4 + i][kk];
            #pragma unroll
            for (int j = 0; j < 4; j++) b[j] = Bs[kk][tx * 4 + j];
            #pragma unroll
            for (int i = 0; i < 4; i++)
                #pragma unroll
                for (int j = 0; j < 4; j++)
                    acc[i][j] = fmaf(a[i], b[j], acc[i][j]);
        }
        __syncthreads();
    }

    #pragma unroll
    for (int i = 0; i < 4; i++) {
        int gr = row0 + ty * 4 + i;
        if (gr < M) {
            float4 v = make_float4(acc[i][0], acc[i][1], acc[i][2], acc[i][3]);
            *(float4*)(C + (size_t)gr * Ncols + col0 + tx * 4) = v;
        }
    }
}

// ---------------- layer 1: per-node attention scalars + init ---------------
__global__ __launch_bounds__(256) void attn1_kernel(
    const float* __restrict__ att_src, const float* __restrict__ att_dst)
{
    int i = blockIdx.x * blockDim.x + threadIdx.x;   // n*HH + h
    if (i >= NN * HH) return;
    int n = i >> 2, h = i & 3;
    const float* xw = g_xw1 + (size_t)n * F1 + h * CC;
    float as = 0.f, ad = 0.f;
    #pragma unroll
    for (int c = 0; c < CC; c++) {
        float v = xw[c];
        as = fmaf(v, att_src[h * CC + c], as);
        ad = fmaf(v, att_dst[h * CC + c], ad);
    }
    g_asrc1[i] = as;
    g_adst1[i] = ad;
    g_m1[i] = -INFINITY;
    g_s1[i] = 0.f;
}

__global__ __launch_bounds__(256) void zero_h1_kernel() {
    int i = blockIdx.x * blockDim.x + threadIdx.x;
    if (i >= NN * F1 / 4) return;
    ((float4*)g_h1)[i] = make_float4(0.f, 0.f, 0.f, 0.f);
}

// ---------------- layer 1 edge passes ---------------------------------------
__global__ __launch_bounds__(256) void edge_max1(
    const int* __restrict__ srcp, const int* __restrict__ dstp, int E, int ET)
{
    int e = blockIdx.x * blockDim.x + threadIdx.x;
    if (e >= ET) return;
    int s, d;
    if (e < E) { s = srcp[e]; d = dstp[e]; } else { s = d = e - E; }
    float4 as = *(const float4*)(g_asrc1 + (size_t)s * 4);
    float4 ad = *(const float4*)(g_adst1 + (size_t)d * 4);
    atomicMaxF(&g_m1[d * 4 + 0], lrelu(as.x + ad.x));
    atomicMaxF(&g_m1[d * 4 + 1], lrelu(as.y + ad.y));
    atomicMaxF(&g_m1[d * 4 + 2], lrelu(as.z + ad.z));
    atomicMaxF(&g_m1[d * 4 + 3], lrelu(as.w + ad.w));
}

__global__ __launch_bounds__(256) void edge_sum1(
    const int* __restrict__ srcp, const int* __restrict__ dstp, int E, int ET)
{
    int e = blockIdx.x * blockDim.x + threadIdx.x;
    if (e >= ET) return;
    int s, d;
    if (e < E) { s = srcp[e]; d = dstp[e]; } else { s = d = e - E; }
    float4 as = *(const float4*)(g_asrc1 + (size_t)s * 4);
    float4 ad = *(const float4*)(g_adst1 + (size_t)d * 4);
    float4 m  = *(const float4*)(g_m1   + (size_t)d * 4);
    atomicAdd(&g_s1[d * 4 + 0], __expf(lrelu(as.x + ad.x) - m.x));
    atomicAdd(&g_s1[d * 4 + 1], __expf(lrelu(as.y + ad.y) - m.y));
    atomicAdd(&g_s1[d * 4 + 2], __expf(lrelu(as.z + ad.z) - m.z));
    atomicAdd(&g_s1[d * 4 + 3], __expf(lrelu(as.w + ad.w) - m.w));
}

// one warp per edge; lane L handles columns [4L, 4L+4) -> head = L>>3
__global__ __launch_bounds__(256) void edge_agg1(
    const int* __restrict__ srcp, const int* __restrict__ dstp, int E, int ET)
{
    int gw = (blockIdx.x * blockDim.x + threadIdx.x) >> 5;
    int lane = threadIdx.x & 31;
    if (gw >= ET) return;
    int s, d;
    if (gw < E) { s = srcp[gw]; d = dstp[gw]; } else { s = d = gw - E; }
    int h = lane >> 3;
    float ev = lrelu(g_asrc1[s * 4 + h] + g_adst1[d * 4 + h]);
    float alpha = __expf(ev - g_m1[d * 4 + h]) / (g_s1[d * 4 + h] + EPSV);
    float4 xv = *(const float4*)(g_xw1 + (size_t)s * F1 + lane * 4);
    float* outp = g_h1 + (size_t)d * F1 + lane * 4;
    asm volatile("red.global.add.v4.f32 [%0], {%1,%2,%3,%4};"
                 :: "l"(outp),
                    "f"(xv.x * alpha), "f"(xv.y * alpha),
                    "f"(xv.z * alpha), "f"(xv.w * alpha)
                 : "memory");
}

// ---------------- bias + BN(eval) + ELU -------------------------------------
__global__ __launch_bounds__(256) void bn_elu_kernel(
    const float* __restrict__ b1,
    const float* __restrict__ gamma, const float* __restrict__ beta,
    const float* __restrict__ mean,  const float* __restrict__ var)
{
    int i = blockIdx.x * blockDim.x + threadIdx.x;
    if (i >= NN * F1) return;
    int c = i & (F1 - 1);
    float h = g_h1[i] + b1[c];
    h = (h - mean[c]) * rsqrtf(var[c] + 1e-5f) * gamma[c] + beta[c];
    g_h1[i] = h > 0.f ? h : expm1f(h);
}

// ---------------- layer 2: per-node attention scalars + init ---------------
__global__ __launch_bounds__(256) void attn2_kernel(
    const float* __restrict__ att_src, const float* __restrict__ att_dst)
{
    int n = blockIdx.x * blockDim.x + threadIdx.x;
    if (n >= NN) return;
    const float* xw = g_xw2 + (size_t)n * F2;
    float as = 0.f, ad = 0.f;
    #pragma unroll
    for (int c = 0; c < F2; c++) {
        float v = xw[c];
        as = fmaf(v, att_src[c], as);
        ad = fmaf(v, att_dst[c], ad);
    }
    g_asrc2[n] = as;
    g_adst2[n] = ad;
    g_m2[n] = -INFINITY;
    g_s2[n] = 0.f;
}

__global__ __launch_bounds__(256) void out_init_kernel(
    float* __restrict__ out, const float* __restrict__ b2)
{
    int i = blockIdx.x * blockDim.x + threadIdx.x;
    if (i >= NN * F2) return;
    out[i] = b2[i & (F2 - 1)];
}

// ---------------- layer 2 edge passes ---------------------------------------
__global__ __launch_bounds__(256) void edge_max2(
    const int* __restrict__ srcp, const int* __restrict__ dstp, int E, int ET)
{
    int e = blockIdx.x * blockDim.x + threadIdx.x;
    if (e >= ET) return;
    int s, d;
    if (e < E) { s = srcp[e]; d = dstp[e]; } else { s = d = e - E; }
    atomicMaxF(&g_m2[d], lrelu(g_asrc2[s] + g_adst2[d]));
}

__global__ __launch_bounds__(256) void edge_sum2(
    const int* __restrict__ srcp, const int* __restrict__ dstp, int E, int ET)
{
    int e = blockIdx.x * blockDim.x + threadIdx.x;
    if (e >= ET) return;
    int s, d;
    if (e < E) { s = srcp[e]; d = dstp[e]; } else { s = d = e - E; }
    atomicAdd(&g_s2[d], __expf(lrelu(g_asrc2[s] + g_adst2[d]) - g_m2[d]));
}

// one warp per edge; lane L handles columns [2L, 2L+2)
__global__ __launch_bounds__(256) void edge_agg2(
    const int* __restrict__ srcp, const int* __restrict__ dstp, int E, int ET,
    float* __restrict__ out)
{
    int gw = (blockIdx.x * blockDim.x + threadIdx.x) >> 5;
    int lane = threadIdx.x & 31;
    if (gw >= ET) return;
    int s, d;
    if (gw < E) { s = srcp[gw]; d = dstp[gw]; } else { s = d = gw - E; }
    float ev = lrelu(g_asrc2[s] + g_adst2[d]);
    float alpha = __expf(ev - g_m2[d]) / (g_s2[d] + EPSV);
    float2 xv = *(const float2*)(g_xw2 + (size_t)s * F2 + lane * 2);
    float* outp = out + (size_t)d * F2 + lane * 2;
    asm volatile("red.global.add.v2.f32 [%0], {%1,%2};"
                 :: "l"(outp), "f"(xv.x * alpha), "f"(xv.y * alpha)
                 : "memory");
}

// ---------------- launch ----------------------------------------------------
extern "C" void kernel_launch(void* const* d_in, const int* in_sizes, int n_in,
                              void* d_out, int out_size)
{
    const float* x        = (const float*)d_in[0];
    const int*   ei       = (const int*)  d_in[1];
    const float* W1       = (const float*)d_in[2];
    const float* att_src1 = (const float*)d_in[3];
    const float* att_dst1 = (const float*)d_in[4];
    const float* b1       = (const float*)d_in[5];
    const float* bn_gamma = (const float*)d_in[6];
    const float* bn_beta  = (const float*)d_in[7];
    const float* bn_mean  = (const float*)d_in[8];
    const float* bn_var   = (const float*)d_in[9];
    const float* W2       = (const float*)d_in[10];
    const float* att_src2 = (const float*)d_in[11];
    const float* att_dst2 = (const float*)d_in[12];
    const float* b2       = (const float*)d_in[13];
    float* out = (float*)d_out;

    int E  = in_sizes[1] / 2;
    int ET = E + NN;
    const int* srcp = ei;
    const int* dstp = ei + E;

    float *p_xw1 = nullptr, *p_h1 = nullptr, *p_xw2 = nullptr;
    cudaGetSymbolAddress((void**)&p_xw1, g_xw1);
    cudaGetSymbolAddress((void**)&p_h1,  g_h1);
    cudaGetSymbolAddress((void**)&p_xw2, g_xw2);

    // ---- layer 1 ----
    {
        dim3 grid(F1 / 64, (NN + 63) / 64);
        gemm_kernel<<<grid, 256>>>(x, W1, p_xw1, NN, F1, F1);
    }
    attn1_kernel<<<(NN * HH + 255) / 256, 256>>>(att_src1, att_dst1);
    zero_h1_kernel<<<(NN * F1 / 4 + 255) / 256, 256>>>();
    edge_max1<<<(ET + 255) / 256, 256>>>(srcp, dstp, E, ET);
    edge_sum1<<<(ET + 255) / 256, 256>>>(srcp, dstp, E, ET);
    edge_agg1<<<(ET + 7) / 8, 256>>>(srcp, dstp, E, ET);
    bn_elu_kernel<<<(NN * F1 + 255) / 256, 256>>>(b1, bn_gamma, bn_beta, bn_mean, bn_var);

    // ---- layer 2 ----
    {
        dim3 grid(F2 / 64, (NN + 63) / 64);
        gemm_kernel<<<grid, 256>>>(p_h1, W2, p_xw2, NN, F2, F1);
    }
    attn2_kernel<<<(NN + 255) / 256, 256>>>(att_src2, att_dst2);
    out_init_kernel<<<(NN * F2 + 255) / 256, 256>>>(out, b2);
    edge_max2<<<(ET + 255) / 256, 256>>>(srcp, dstp, E, ET);
    edge_sum2<<<(ET + 255) / 256, 256>>>(srcp, dstp, E, ET);
    edge_agg2<<<(ET + 7) / 8, 256>>>(srcp, dstp, E, ET, out);
}

// round 2
// speedup vs baseline: 2.0904x; 2.0904x over previous
#include <cuda_runtime.h>
#include <math.h>

#define NN 50000
#define HH 4
#define CC 32
#define F1 128
#define F2 64
#define NEG 0.2f
#define EPSV 1e-16f
#define EMAX 1700000   // capacity for E + N self loops

// ---------------- scratch (device globals; no allocations allowed) ----------
__device__ float g_xw1[NN * F1];     // x @ W1            [N,128]
__device__ float g_h1 [NN * F1];     // layer1 output     [N,128]
__device__ float g_asrc1[NN * HH];
__device__ float g_adst1[NN * HH];
__device__ float g_xw2[NN * F2];     // h @ W2            [N,64]
__device__ float g_asrc2[NN];
__device__ float g_adst2[NN];
__device__ int   g_deg[NN];          // in-degree (incl self loop)
__device__ int   g_off[NN];          // CSR segment start
__device__ int   g_cur[NN];          // scatter cursor
__device__ int   g_csr[EMAX];        // src node per edge, grouped by dst

__device__ __forceinline__ float lrelu(float v) { return v > 0.f ? v : NEG * v; }

// ---------------- SGEMM: C[M,Ncols] = A[M,K] @ B[K,Ncols] -------------------
__global__ __launch_bounds__(256) void gemm_kernel(
    const float* __restrict__ A, const float* __restrict__ B,
    float* __restrict__ C, int M, int Ncols, int K)
{
    const int BM = 64, BN = 64, BK = 16;
    __shared__ float As[BM][BK];
    __shared__ float Bs[BK][BN];

    int tid = threadIdx.x;
    int tx = tid & 15;
    int ty = tid >> 4;
    int row0 = blockIdx.y * BM;
    int col0 = blockIdx.x * BN;

    float acc[4][4] = {};

    for (int k0 = 0; k0 < K; k0 += BK) {
        {
            int r  = tid >> 2;
            int c4 = (tid & 3) * 4;
            int gr = row0 + r;
            float4 v = make_float4(0.f, 0.f, 0.f, 0.f);
            if (gr < M) v = *(const float4*)(A + (size_t)gr * K + k0 + c4);
            As[r][c4 + 0] = v.x; As[r][c4 + 1] = v.y;
            As[r][c4 + 2] = v.z; As[r][c4 + 3] = v.w;
        }
        {
            int r  = tid >> 4;
            int c4 = (tid & 15) * 4;
            float4 v = *(const float4*)(B + (size_t)(k0 + r) * Ncols + col0 + c4);
            Bs[r][c4 + 0] = v.x; Bs[r][c4 + 1] = v.y;
            Bs[r][c4 + 2] = v.z; Bs[r][c4 + 3] = v.w;
        }
        __syncthreads();

        #pragma unroll
        for (int kk = 0; kk < BK; kk++) {
            float a[4], b[4];
            #pragma unroll
            for (int i = 0; i < 4; i++) a[i] = As[ty * 4 + i][kk];
            #pragma unroll
            for (int j = 0; j < 4; j++) b[j] = Bs[kk][tx * 4 + j];
            #pragma unroll
            for (int i = 0; i < 4; i++)
                #pragma unroll
                for (int j = 0; j < 4; j++)
                    acc[i][j] = fmaf(a[i], b[j], acc[i][j]);
        }
        __syncthreads();
    }

    #pragma unroll
    for (int i = 0; i < 4; i++) {
        int gr = row0 + ty * 4 + i;
        if (gr < M) {
            float4 v = make_float4(acc[i][0], acc[i][1], acc[i][2], acc[i][3]);
            *(float4*)(C + (size_t)gr * Ncols + col0 + tx * 4) = v;
        }
    }
}

// ---------------- CSR build --------------------------------------------------
__global__ __launch_bounds__(256) void init_deg_kernel() {
    int i = blockIdx.x * blockDim.x + threadIdx.x;
    if (i < NN) g_deg[i] = 1;     // self loop
}

__global__ __launch_bounds__(256) void hist_kernel(const int* __restrict__ dstp, int E) {
    int e = blockIdx.x * blockDim.x + threadIdx.x;
    if (e < E) atomicAdd(&g_deg[dstp[e]], 1);
}

// single-block exclusive scan over g_deg -> g_off, g_cur
__global__ __launch_bounds__(1024) void scan_kernel() {
    __shared__ int warp_sums[32];
    int tid = threadIdx.x, lane = tid & 31, wid = tid >> 5;
    int carry = 0;
    for (int base = 0; base < NN; base += 1024) {
        int idx = base + tid;
        int v = (idx < NN) ? g_deg[idx] : 0;
        int x = v;
        #pragma unroll
        for (int o = 1; o < 32; o <<= 1) {
            int t = __shfl_up_sync(0xffffffffu, x, o);
            if (lane >= o) x += t;
        }
        if (lane == 31) warp_sums[wid] = x;
        __syncthreads();
        if (wid == 0) {
            int s = warp_sums[lane];
            #pragma unroll
            for (int o = 1; o < 32; o <<= 1) {
                int t = __shfl_up_sync(0xffffffffu, s, o);
                if (lane >= o) s += t;
            }
            warp_sums[lane] = s;
        }
        __syncthreads();
        int pre = (wid > 0 ? warp_sums[wid - 1] : 0) + (x - v) + carry;
        if (idx < NN) { g_off[idx] = pre; g_cur[idx] = pre; }
        int total = warp_sums[31];
        __syncthreads();
        carry += total;
    }
}

__global__ __launch_bounds__(256) void scatter_kernel(
    const int* __restrict__ srcp, const int* __restrict__ dstp, int E, int ET)
{
    int e = blockIdx.x * blockDim.x + threadIdx.x;
    if (e >= ET) return;
    int s, d;
    if (e < E) { s = srcp[e]; d = dstp[e]; } else { s = d = e - E; }
    int pos = atomicAdd(&g_cur[d], 1);
    g_csr[pos] = s;
}

// ---------------- per-node attention scalars --------------------------------
__global__ __launch_bounds__(256) void attn1_kernel(
    const float* __restrict__ att_src, const float* __restrict__ att_dst)
{
    int i = blockIdx.x * blockDim.x + threadIdx.x;   // n*HH + h
    if (i >= NN * HH) return;
    int n = i >> 2, h = i & 3;
    const float* xw = g_xw1 + (size_t)n * F1 + h * CC;
    float as = 0.f, ad = 0.f;
    #pragma unroll
    for (int c = 0; c < CC; c++) {
        float v = xw[c];
        as = fmaf(v, att_src[h * CC + c], as);
        ad = fmaf(v, att_dst[h * CC + c], ad);
    }
    g_asrc1[i] = as;
    g_adst1[i] = ad;
}

__global__ __launch_bounds__(256) void attn2_kernel(
    const float* __restrict__ att_src, const float* __restrict__ att_dst)
{
    int n = blockIdx.x * blockDim.x + threadIdx.x;
    if (n >= NN) return;
    const float* xw = g_xw2 + (size_t)n * F2;
    float as = 0.f, ad = 0.f;
    #pragma unroll
    for (int c = 0; c < F2; c++) {
        float v = xw[c];
        as = fmaf(v, att_src[c], as);
        ad = fmaf(v, att_dst[c], ad);
    }
    g_asrc2[n] = as;
    g_adst2[n] = ad;
}

// ---------------- layer 1 fused gather: softmax-agg + bias + BN + ELU -------
// one warp per dst node; lane handles 4 columns (head = lane>>3)
__global__ __launch_bounds__(256) void agg1_kernel(
    const float* __restrict__ b1,
    const float* __restrict__ gamma, const float* __restrict__ beta,
    const float* __restrict__ mean,  const float* __restrict__ var)
{
    int d = (blockIdx.x * blockDim.x + threadIdx.x) >> 5;
    int lane = threadIdx.x & 31;
    if (d >= NN) return;

    int start = g_off[d];
    int deg   = g_deg[d];
    int h = lane >> 3;
    float ad = g_adst1[d * 4 + h];

    float4 acc = make_float4(0.f, 0.f, 0.f, 0.f);
    float ssum = 0.f;

    for (int i = 0; i < deg; i += 32) {
        int remain = deg - i;
        int cnt = remain < 32 ? remain : 32;
        int sj = (lane < cnt) ? g_csr[start + i + lane] : 0;
        #pragma unroll 4
        for (int k = 0; k < cnt; k++) {
            int s = __shfl_sync(0xffffffffu, sj, k);
            float e = g_asrc1[s * 4 + h] + ad;
            float w = __expf(e > 0.f ? e : NEG * e);
            float4 xv = *(const float4*)(g_xw1 + (size_t)s * F1 + lane * 4);
            ssum += w;
            acc.x = fmaf(w, xv.x, acc.x);
            acc.y = fmaf(w, xv.y, acc.y);
            acc.z = fmaf(w, xv.z, acc.z);
            acc.w = fmaf(w, xv.w, acc.w);
        }
    }

    float inv = 1.f / (ssum + EPSV);
    int c0 = lane * 4;
    float o[4] = { acc.x * inv, acc.y * inv, acc.z * inv, acc.w * inv };
    #pragma unroll
    for (int j = 0; j < 4; j++) {
        int c = c0 + j;
        float hv = o[j] + b1[c];
        hv = (hv - mean[c]) * rsqrtf(var[c] + 1e-5f) * gamma[c] + beta[c];
        o[j] = hv > 0.f ? hv : expm1f(hv);
    }
    *(float4*)(g_h1 + (size_t)d * F1 + c0) = make_float4(o[0], o[1], o[2], o[3]);
}

// ---------------- layer 2 fused gather: softmax-agg + bias -> out -----------
// one warp per dst node; lane handles 2 columns (single head)
__global__ __launch_bounds__(256) void agg2_kernel(
    float* __restrict__ out, const float* __restrict__ b2)
{
    int d = (blockIdx.x * blockDim.x + threadIdx.x) >> 5;
    int lane = threadIdx.x & 31;
    if (d >= NN) return;

    int start = g_off[d];
    int deg   = g_deg[d];
    float ad = g_adst2[d];

    float2 acc = make_float2(0.f, 0.f);
    float ssum = 0.f;

    for (int i = 0; i < deg; i += 32) {
        int remain = deg - i;
        int cnt = remain < 32 ? remain : 32;
        int sj = (lane < cnt) ? g_csr[start + i + lane] : 0;
        #pragma unroll 4
        for (int k = 0; k < cnt; k++) {
            int s = __shfl_sync(0xffffffffu, sj, k);
            float e = g_asrc2[s] + ad;
            float w = __expf(e > 0.f ? e : NEG * e);
            float2 xv = *(const float2*)(g_xw2 + (size_t)s * F2 + lane * 2);
            ssum += w;
            acc.x = fmaf(w, xv.x, acc.x);
            acc.y = fmaf(w, xv.y, acc.y);
        }
    }

    float inv = 1.f / (ssum + EPSV);
    int c0 = lane * 2;
    float2 ov;
    ov.x = acc.x * inv + b2[c0 + 0];
    ov.y = acc.y * inv + b2[c0 + 1];
    *(float2*)(out + (size_t)d * F2 + c0) = ov;
}

// ---------------- launch ----------------------------------------------------
extern "C" void kernel_launch(void* const* d_in, const int* in_sizes, int n_in,
                              void* d_out, int out_size)
{
    const float* x        = (const float*)d_in[0];
    const int*   ei       = (const int*)  d_in[1];
    const float* W1       = (const float*)d_in[2];
    const float* att_src1 = (const float*)d_in[3];
    const float* att_dst1 = (const float*)d_in[4];
    const float* b1       = (const float*)d_in[5];
    const float* bn_gamma = (const float*)d_in[6];
    const float* bn_beta  = (const float*)d_in[7];
    const float* bn_mean  = (const float*)d_in[8];
    const float* bn_var   = (const float*)d_in[9];
    const float* W2       = (const float*)d_in[10];
    const float* att_src2 = (const float*)d_in[11];
    const float* att_dst2 = (const float*)d_in[12];
    const float* b2       = (const float*)d_in[13];
    float* out = (float*)d_out;

    int E  = in_sizes[1] / 2;
    int ET = E + NN;
    const int* srcp = ei;
    const int* dstp = ei + E;

    float *p_xw1 = nullptr, *p_h1 = nullptr, *p_xw2 = nullptr;
    cudaGetSymbolAddress((void**)&p_xw1, g_xw1);
    cudaGetSymbolAddress((void**)&p_h1,  g_h1);
    cudaGetSymbolAddress((void**)&p_xw2, g_xw2);

    // ---- CSR build (shared by both layers) ----
    init_deg_kernel<<<(NN + 255) / 256, 256>>>();
    hist_kernel<<<(E + 255) / 256, 256>>>(dstp, E);
    scan_kernel<<<1, 1024>>>();
    scatter_kernel<<<(ET + 255) / 256, 256>>>(srcp, dstp, E, ET);

    // ---- layer 1 ----
    {
        dim3 grid(F1 / 64, (NN + 63) / 64);
        gemm_kernel<<<grid, 256>>>(x, W1, p_xw1, NN, F1, F1);
    }
    attn1_kernel<<<(NN * HH + 255) / 256, 256>>>(att_src1, att_dst1);
    agg1_kernel<<<(NN * 32 + 255) / 256, 256>>>(b1, bn_gamma, bn_beta, bn_mean, bn_var);

    // ---- layer 2 ----
    {
        dim3 grid(F2 / 64, (NN + 63) / 64);
        gemm_kernel<<<grid, 256>>>(p_h1, W2, p_xw2, NN, F2, F1);
    }
    attn2_kernel<<<(NN + 255) / 256, 256>>>(att_src2, att_dst2);
    agg2_kernel<<<(NN * 32 + 255) / 256, 256>>>(out, b2);
}

// round 4
// speedup vs baseline: 2.2347x; 1.0690x over previous
#include <cuda_runtime.h>
#include <math.h>
#include <stdint.h>

#define NN 50000
#define HH 4
#define CC 32
#define F1 128
#define F2 64
#define NEG 0.2f
#define EPSV 1e-16f
#define EMAX 1700000   // capacity for E + N self loops

// ---------------- scratch (device globals; no allocations allowed) ----------
__device__ float g_xw1[NN * F1];     // x @ W1            [N,128]
__device__ float g_h1 [NN * F1];     // layer1 output     [N,128]
__device__ float g_asrc1[NN * HH];
__device__ float g_adst1[NN * HH];
__device__ float g_xw2[NN * F2];     // h @ W2            [N,64]
__device__ float g_asrc2[NN];
__device__ float g_adst2[NN];
__device__ int   g_deg[NN];          // in-degree (incl self loop)
__device__ int   g_off[NN];          // CSR segment start
__device__ int   g_cur[NN];          // scatter cursor
__device__ int   g_csr[EMAX];        // src node per edge, grouped by dst

__device__ __forceinline__ float lrelu(float v) { return v > 0.f ? v : NEG * v; }

// ---------------- SGEMM: C[M,BN] = A[M,128] @ B[128,BN], grid.x == 1 --------
// BM=128, BK=8, 8x8 microtile, double-buffered smem, FFMA-bound.
template<int BN, int NT>
__global__ __launch_bounds__(NT) void gemm_tc(
    const float* __restrict__ A, const float* __restrict__ B,
    float* __restrict__ C, int M)
{
    const int BM = 128, BK = 8, KTOT = 128;
    const int TX = BN / 8;                 // threads along N
    __shared__ float As[2][BK * BM];       // [k][row] transposed
    __shared__ float Bs[2][BK * BN];       // [k][col]

    int tid = threadIdx.x;
    int tx = tid % TX;
    int ty = tid / TX;
    int row0 = blockIdx.y * BM;

    float acc[8][8] = {};

    // tile loader: global -> smem[buf]
    auto load_tile = [&](int buf, int kt) {
        int k0 = kt * BK;
        #pragma unroll
        for (int idx = tid; idx < BM * BK / 4; idx += NT) {
            int row = idx >> 1;            // 2 float4 chunks per row (BK=8)
            int kc  = (idx & 1) * 4;
            int gr = row0 + row;
            float4 v = make_float4(0.f, 0.f, 0.f, 0.f);
            if (gr < M) v = *(const float4*)(A + (size_t)gr * KTOT + k0 + kc);
            As[buf][(kc + 0) * BM + row] = v.x;
            As[buf][(kc + 1) * BM + row] = v.y;
            As[buf][(kc + 2) * BM + row] = v.z;
            As[buf][(kc + 3) * BM + row] = v.w;
        }
        #pragma unroll
        for (int idx = tid; idx < BK * BN / 4; idx += NT) {
            int r  = idx / (BN / 4);
            int c4 = (idx % (BN / 4)) * 4;
            *(float4*)&Bs[buf][r * BN + c4] =
                *(const float4*)(B + (size_t)(k0 + r) * BN + c4);
        }
    };

    load_tile(0, 0);
    __syncthreads();

    int buf = 0;
    for (int kt = 0; kt < KTOT / BK; kt++) {
        if (kt + 1 < KTOT / BK) load_tile(buf ^ 1, kt + 1);
        #pragma unroll
        for (int kk = 0; kk < BK; kk++) {
            float4 a0 = *(const float4*)&As[buf][kk * BM + ty * 8];
            float4 a1 = *(const float4*)&As[buf][kk * BM + ty * 8 + 4];
            float4 b0 = *(const float4*)&Bs[buf][kk * BN + tx * 8];
            float4 b1 = *(const float4*)&Bs[buf][kk * BN + tx * 8 + 4];
            float av[8] = {a0.x,a0.y,a0.z,a0.w,a1.x,a1.y,a1.z,a1.w};
            float bv[8] = {b0.x,b0.y,b0.z,b0.w,b1.x,b1.y,b1.z,b1.w};
            #pragma unroll
            for (int i = 0; i < 8; i++)
                #pragma unroll
                for (int j = 0; j < 8; j++)
                    acc[i][j] = fmaf(av[i], bv[j], acc[i][j]);
        }
        __syncthreads();
        buf ^= 1;
    }

    #pragma unroll
    for (int i = 0; i < 8; i++) {
        int gr = row0 + ty * 8 + i;
        if (gr < M) {
            float4 v0 = make_float4(acc[i][0], acc[i][1], acc[i][2], acc[i][3]);
            float4 v1 = make_float4(acc[i][4], acc[i][5], acc[i][6], acc[i][7]);
            *(float4*)(C + (size_t)gr * BN + tx * 8)     = v0;
            *(float4*)(C + (size_t)gr * BN + tx * 8 + 4) = v1;
        }
    }
}

// ---------------- CSR build --------------------------------------------------
__global__ __launch_bounds__(256) void init_deg_kernel() {
    int i = blockIdx.x * blockDim.x + threadIdx.x;
    if (i < NN) g_deg[i] = 1;     // self loop
}

__global__ __launch_bounds__(256) void hist4_kernel(const int* __restrict__ dstp, int E) {
    int i = blockIdx.x * blockDim.x + threadIdx.x;
    int e4 = i * 4;
    if (e4 + 3 < E) {
        int4 d = *(const int4*)(dstp + e4);
        atomicAdd(&g_deg[d.x], 1);
        atomicAdd(&g_deg[d.y], 1);
        atomicAdd(&g_deg[d.z], 1);
        atomicAdd(&g_deg[d.w], 1);
    } else {
        for (int e = e4; e < E; e++) atomicAdd(&g_deg[dstp[e]], 1);
    }
}

__global__ __launch_bounds__(256) void hist1_kernel(const int* __restrict__ dstp, int E) {
    int e = blockIdx.x * blockDim.x + threadIdx.x;
    if (e < E) atomicAdd(&g_deg[dstp[e]], 1);
}

// single-block exclusive scan over g_deg -> g_off, g_cur
__global__ __launch_bounds__(1024) void scan_kernel() {
    __shared__ int warp_sums[32];
    int tid = threadIdx.x, lane = tid & 31, wid = tid >> 5;
    int carry = 0;
    for (int base = 0; base < NN; base += 1024) {
        int idx = base + tid;
        int v = (idx < NN) ? g_deg[idx] : 0;
        int x = v;
        #pragma unroll
        for (int o = 1; o < 32; o <<= 1) {
            int t = __shfl_up_sync(0xffffffffu, x, o);
            if (lane >= o) x += t;
        }
        if (lane == 31) warp_sums[wid] = x;
        __syncthreads();
        if (wid == 0) {
            int s = warp_sums[lane];
            #pragma unroll
            for (int o = 1; o < 32; o <<= 1) {
                int t = __shfl_up_sync(0xffffffffu, s, o);
                if (lane >= o) s += t;
            }
            warp_sums[lane] = s;
        }
        __syncthreads();
        int pre = (wid > 0 ? warp_sums[wid - 1] : 0) + (x - v) + carry;
        if (idx < NN) { g_off[idx] = pre; g_cur[idx] = pre; }
        int total = warp_sums[31];
        __syncthreads();
        carry += total;
    }
}

__global__ __launch_bounds__(256) void scatter4_kernel(
    const int* __restrict__ srcp, const int* __restrict__ dstp, int E)
{
    int i = blockIdx.x * blockDim.x + threadIdx.x;
    int e4 = i * 4;
    if (e4 + 3 < E) {
        int4 s = *(const int4*)(srcp + e4);
        int4 d = *(const int4*)(dstp + e4);
        g_csr[atomicAdd(&g_cur[d.x], 1)] = s.x;
        g_csr[atomicAdd(&g_cur[d.y], 1)] = s.y;
        g_csr[atomicAdd(&g_cur[d.z], 1)] = s.z;
        g_csr[atomicAdd(&g_cur[d.w], 1)] = s.w;
    } else {
        for (int e = e4; e < E; e++)
            g_csr[atomicAdd(&g_cur[dstp[e]], 1)] = srcp[e];
    }
}

__global__ __launch_bounds__(256) void scatter1_kernel(
    const int* __restrict__ srcp, const int* __restrict__ dstp, int E)
{
    int e = blockIdx.x * blockDim.x + threadIdx.x;
    if (e < E) g_csr[atomicAdd(&g_cur[dstp[e]], 1)] = srcp[e];
}

__global__ __launch_bounds__(256) void self_scatter_kernel() {
    int i = blockIdx.x * blockDim.x + threadIdx.x;
    if (i < NN) g_csr[atomicAdd(&g_cur[i], 1)] = i;
}

// ---------------- per-node attention scalars --------------------------------
__global__ __launch_bounds__(256) void attn1_kernel(
    const float* __restrict__ att_src, const float* __restrict__ att_dst)
{
    int i = blockIdx.x * blockDim.x + threadIdx.x;   // n*HH + h
    if (i >= NN * HH) return;
    int n = i >> 2, h = i & 3;
    const float* xw = g_xw1 + (size_t)n * F1 + h * CC;
    float as = 0.f, ad = 0.f;
    #pragma unroll
    for (int c = 0; c < CC; c++) {
        float v = xw[c];
        as = fmaf(v, att_src[h * CC + c], as);
        ad = fmaf(v, att_dst[h * CC + c], ad);
    }
    g_asrc1[i] = as;
    g_adst1[i] = ad;
}

__global__ __launch_bounds__(256) void attn2_kernel(
    const float* __restrict__ att_src, const float* __restrict__ att_dst)
{
    int n = blockIdx.x * blockDim.x + threadIdx.x;
    if (n >= NN) return;
    const float* xw = g_xw2 + (size_t)n * F2;
    float as = 0.f, ad = 0.f;
    #pragma unroll
    for (int c = 0; c < F2; c++) {
        float v = xw[c];
        as = fmaf(v, att_src[c], as);
        ad = fmaf(v, att_dst[c], ad);
    }
    g_asrc2[n] = as;
    g_adst2[n] = ad;
}

// ---------------- layer 1 fused gather: softmax-agg + bias + BN + ELU -------
__global__ __launch_bounds__(256) void agg1_kernel(
    const float* __restrict__ b1,
    const float* __restrict__ gamma, const float* __restrict__ beta,
    const float* __restrict__ mean,  const float* __restrict__ var)
{
    int d = (blockIdx.x * blockDim.x + threadIdx.x) >> 5;
    int lane = threadIdx.x & 31;
    if (d >= NN) return;

    int start = g_off[d];
    int deg   = g_deg[d];
    int h = lane >> 3;
    float ad = g_adst1[d * 4 + h];

    float4 acc = make_float4(0.f, 0.f, 0.f, 0.f);
    float ssum = 0.f;

    for (int i = 0; i < deg; i += 32) {
        int remain = deg - i;
        int cnt = remain < 32 ? remain : 32;
        int sj = (lane < cnt) ? g_csr[start + i + lane] : 0;
        #pragma unroll 4
        for (int k = 0; k < cnt; k++) {
            int s = __shfl_sync(0xffffffffu, sj, k);
            float e = g_asrc1[s * 4 + h] + ad;
            float w = __expf(e > 0.f ? e : NEG * e);
            float4 xv = *(const float4*)(g_xw1 + (size_t)s * F1 + lane * 4);
            ssum += w;
            acc.x = fmaf(w, xv.x, acc.x);
            acc.y = fmaf(w, xv.y, acc.y);
            acc.z = fmaf(w, xv.z, acc.z);
            acc.w = fmaf(w, xv.w, acc.w);
        }
    }

    float inv = 1.f / (ssum + EPSV);
    int c0 = lane * 4;
    float o[4] = { acc.x * inv, acc.y * inv, acc.z * inv, acc.w * inv };
    #pragma unroll
    for (int j = 0; j < 4; j++) {
        int c = c0 + j;
        float hv = o[j] + b1[c];
        hv = (hv - mean[c]) * rsqrtf(var[c] + 1e-5f) * gamma[c] + beta[c];
        o[j] = hv > 0.f ? hv : expm1f(hv);
    }
    *(float4*)(g_h1 + (size_t)d * F1 + c0) = make_float4(o[0], o[1], o[2], o[3]);
}

// ---------------- layer 2 fused gather: softmax-agg + bias -> out -----------
__global__ __launch_bounds__(256) void agg2_kernel(
    float* __restrict__ out, const float* __restrict__ b2)
{
    int d = (blockIdx.x * blockDim.x + threadIdx.x) >> 5;
    int lane = threadIdx.x & 31;
    if (d >= NN) return;

    int start = g_off[d];
    int deg   = g_deg[d];
    float ad = g_adst2[d];

    float2 acc = make_float2(0.f, 0.f);
    float ssum = 0.f;

    for (int i = 0; i < deg; i += 32) {
        int remain = deg - i;
        int cnt = remain < 32 ? remain : 32;
        int sj = (lane < cnt) ? g_csr[start + i + lane] : 0;
        #pragma unroll 4
        for (int k = 0; k < cnt; k++) {
            int s = __shfl_sync(0xffffffffu, sj, k);
            float e = g_asrc2[s] + ad;
            float w = __expf(e > 0.f ? e : NEG * e);
            float2 xv = *(const float2*)(g_xw2 + (size_t)s * F2 + lane * 2);
            ssum += w;
            acc.x = fmaf(w, xv.x, acc.x);
            acc.y = fmaf(w, xv.y, acc.y);
        }
    }

    float inv = 1.f / (ssum + EPSV);
    int c0 = lane * 2;
    float2 ov;
    ov.x = acc.x * inv + b2[c0 + 0];
    ov.y = acc.y * inv + b2[c0 + 1];
    *(float2*)(out + (size_t)d * F2 + c0) = ov;
}

// ---------------- launch ----------------------------------------------------
extern "C" void kernel_launch(void* const* d_in, const int* in_sizes, int n_in,
                              void* d_out, int out_size)
{
    const float* x        = (const float*)d_in[0];
    const int*   ei       = (const int*)  d_in[1];
    const float* W1       = (const float*)d_in[2];
    const float* att_src1 = (const float*)d_in[3];
    const float* att_dst1 = (const float*)d_in[4];
    const float* b1       = (const float*)d_in[5];
    const float* bn_gamma = (const float*)d_in[6];
    const float* bn_beta  = (const float*)d_in[7];
    const float* bn_mean  = (const float*)d_in[8];
    const float* bn_var   = (const float*)d_in[9];
    const float* W2       = (const float*)d_in[10];
    const float* att_src2 = (const float*)d_in[11];
    const float* att_dst2 = (const float*)d_in[12];
    const float* b2       = (const float*)d_in[13];
    float* out = (float*)d_out;

    int E  = in_sizes[1] / 2;
    const int* srcp = ei;
    const int* dstp = ei + E;

    float *p_xw1 = nullptr, *p_h1 = nullptr, *p_xw2 = nullptr;
    cudaGetSymbolAddress((void**)&p_xw1, g_xw1);
    cudaGetSymbolAddress((void**)&p_h1,  g_h1);
    cudaGetSymbolAddress((void**)&p_xw2, g_xw2);

    // side stream + events (created once, on the non-captured correctness call)
    static cudaStream_t s_side = nullptr;
    static cudaEvent_t ev_fork = nullptr, ev_join = nullptr;
    if (!s_side) {
        cudaStreamCreateWithFlags(&s_side, cudaStreamNonBlocking);
        cudaEventCreateWithFlags(&ev_fork, cudaEventDisableTiming);
        cudaEventCreateWithFlags(&ev_join, cudaEventDisableTiming);
    }

    bool vec_ok = (E % 4 == 0) &&
                  ((((uintptr_t)srcp) & 15u) == 0) &&
                  ((((uintptr_t)dstp) & 15u) == 0);

    // ---- fork: CSR build on side stream, GEMM1+attn1 on main --------------
    cudaEventRecord(ev_fork, 0);
    cudaStreamWaitEvent(s_side, ev_fork, 0);

    init_deg_kernel<<<(NN + 255) / 256, 256, 0, s_side>>>();
    if (vec_ok) {
        hist4_kernel<<<(E / 4 + 255) / 256, 256, 0, s_side>>>(dstp, E);
    } else {
        hist1_kernel<<<(E + 255) / 256, 256, 0, s_side>>>(dstp, E);
    }
    scan_kernel<<<1, 1024, 0, s_side>>>();
    if (vec_ok) {
        scatter4_kernel<<<(E / 4 + 255) / 256, 256, 0, s_side>>>(srcp, dstp, E);
    } else {
        scatter1_kernel<<<(E + 255) / 256, 256, 0, s_side>>>(srcp, dstp, E);
    }
    self_scatter_kernel<<<(NN + 255) / 256, 256, 0, s_side>>>();

    {
        dim3 grid(1, (NN + 127) / 128);
        gemm_tc<F1, 256><<<grid, 256>>>(x, W1, p_xw1, NN);
    }
    attn1_kernel<<<(NN * HH + 255) / 256, 256>>>(att_src1, att_dst1);

    // ---- join ---------------------------------------------------------------
    cudaEventRecord(ev_join, s_side);
    cudaStreamWaitEvent(0, ev_join, 0);

    // ---- layer 1 aggregate + layer 2 ---------------------------------------
    agg1_kernel<<<(NN * 32 + 255) / 256, 256>>>(b1, bn_gamma, bn_beta, bn_mean, bn_var);
    {
        dim3 grid(1, (NN + 127) / 128);
        gemm_tc<F2, 128><<<grid, 128>>>(p_h1, W2, p_xw2, NN);
    }
    attn2_kernel<<<(NN + 255) / 256, 256>>>(att_src2, att_dst2);
    agg2_kernel<<<(NN * 32 + 255) / 256, 256>>>(out, b2);
}

// round 5
// speedup vs baseline: 2.2995x; 1.0290x over previous
#include <cuda_runtime.h>
#include <cuda_fp16.h>
#include <math.h>
#include <stdint.h>

#define NN 50000
#define HH 4
#define CC 32
#define F1 128
#define F2 64
#define NEG 0.2f
#define EPSV 1e-16f
#define EMAX 1700000   // capacity for E + N self loops
#define NBLK ((NN + 255) / 256)

// ---------------- scratch (device globals; no allocations allowed) ----------
__device__ float  g_xw1[NN * F1];     // x @ W1 fp32 (for attn1)
__device__ __align__(16) __half g_xw1h[NN * F1];  // half copy (for agg1 gather)
__device__ float  g_h1 [NN * F1];     // layer1 output
__device__ float  g_asrc1[NN * HH];
__device__ float  g_adst1[NN * HH];
__device__ float  g_xw2[NN * F2];     // h @ W2 fp32 (for attn2)
__device__ __align__(16) __half g_xw2h[NN * F2];  // half copy (for agg2 gather)
__device__ float  g_asrc2[NN];
__device__ float  g_adst2[NN];
__device__ int    g_deg[NN];          // in-degree (incl self loop)
__device__ int    g_off[NN];          // CSR segment start
__device__ int    g_cur[NN];          // scatter cursor
__device__ int    g_bsum[256];        // block sums for scan
__device__ int    g_csr[EMAX];        // src node per edge, grouped by dst

// ---------------- SGEMM: C[M,BN] = A[M,128] @ B[128,BN], grid.x == 1 --------
// BM=128, BK=8, 8x8 microtile, double-buffered smem; also writes half copy.
template<int BN, int NT>
__global__ __launch_bounds__(NT) void gemm_tc(
    const float* __restrict__ A, const float* __restrict__ B,
    float* __restrict__ C, __half* __restrict__ Ch, int M)
{
    const int BM = 128, BK = 8, KTOT = 128;
    const int TX = BN / 8;
    __shared__ float As[2][BK * BM];       // [k][row] transposed
    __shared__ float Bs[2][BK * BN];       // [k][col]

    int tid = threadIdx.x;
    int tx = tid % TX;
    int ty = tid / TX;
    int row0 = blockIdx.y * BM;

    float acc[8][8] = {};

    auto load_tile = [&](int buf, int kt) {
        int k0 = kt * BK;
        #pragma unroll
        for (int idx = tid; idx < BM * BK / 4; idx += NT) {
            int row = idx >> 1;
            int kc  = (idx & 1) * 4;
            int gr = row0 + row;
            float4 v = make_float4(0.f, 0.f, 0.f, 0.f);
            if (gr < M) v = *(const float4*)(A + (size_t)gr * KTOT + k0 + kc);
            As[buf][(kc + 0) * BM + row] = v.x;
            As[buf][(kc + 1) * BM + row] = v.y;
            As[buf][(kc + 2) * BM + row] = v.z;
            As[buf][(kc + 3) * BM + row] = v.w;
        }
        #pragma unroll
        for (int idx = tid; idx < BK * BN / 4; idx += NT) {
            int r  = idx / (BN / 4);
            int c4 = (idx % (BN / 4)) * 4;
            *(float4*)&Bs[buf][r * BN + c4] =
                *(const float4*)(B + (size_t)(k0 + r) * BN + c4);
        }
    };

    load_tile(0, 0);
    __syncthreads();

    int buf = 0;
    for (int kt = 0; kt < KTOT / BK; kt++) {
        if (kt + 1 < KTOT / BK) load_tile(buf ^ 1, kt + 1);
        #pragma unroll
        for (int kk = 0; kk < BK; kk++) {
            float4 a0 = *(const float4*)&As[buf][kk * BM + ty * 8];
            float4 a1 = *(const float4*)&As[buf][kk * BM + ty * 8 + 4];
            float4 b0 = *(const float4*)&Bs[buf][kk * BN + tx * 8];
            float4 b1 = *(const float4*)&Bs[buf][kk * BN + tx * 8 + 4];
            float av[8] = {a0.x,a0.y,a0.z,a0.w,a1.x,a1.y,a1.z,a1.w};
            float bv[8] = {b0.x,b0.y,b0.z,b0.w,b1.x,b1.y,b1.z,b1.w};
            #pragma unroll
            for (int i = 0; i < 8; i++)
                #pragma unroll
                for (int j = 0; j < 8; j++)
                    acc[i][j] = fmaf(av[i], bv[j], acc[i][j]);
        }
        __syncthreads();
        buf ^= 1;
    }

    #pragma unroll
    for (int i = 0; i < 8; i++) {
        int gr = row0 + ty * 8 + i;
        if (gr < M) {
            float4 v0 = make_float4(acc[i][0], acc[i][1], acc[i][2], acc[i][3]);
            float4 v1 = make_float4(acc[i][4], acc[i][5], acc[i][6], acc[i][7]);
            *(float4*)(C + (size_t)gr * BN + tx * 8)     = v0;
            *(float4*)(C + (size_t)gr * BN + tx * 8 + 4) = v1;
            __half2 p0 = __floats2half2_rn(acc[i][0], acc[i][1]);
            __half2 p1 = __floats2half2_rn(acc[i][2], acc[i][3]);
            __half2 p2 = __floats2half2_rn(acc[i][4], acc[i][5]);
            __half2 p3 = __floats2half2_rn(acc[i][6], acc[i][7]);
            uint4 u = make_uint4(*(unsigned*)&p0, *(unsigned*)&p1,
                                 *(unsigned*)&p2, *(unsigned*)&p3);
            *(uint4*)(Ch + (size_t)gr * BN + tx * 8) = u;
        }
    }
}

// ---------------- CSR build --------------------------------------------------
__global__ __launch_bounds__(256) void init_deg_kernel() {
    int i = blockIdx.x * blockDim.x + threadIdx.x;
    if (i < NN) g_deg[i] = 1;     // self loop
}

__global__ __launch_bounds__(256) void hist8_kernel(const int* __restrict__ dstp, int E) {
    int i = blockIdx.x * blockDim.x + threadIdx.x;
    int e8 = i * 8;
    if (e8 + 7 < E) {
        int4 a = *(const int4*)(dstp + e8);
        int4 b = *(const int4*)(dstp + e8 + 4);
        atomicAdd(&g_deg[a.x], 1); atomicAdd(&g_deg[a.y], 1);
        atomicAdd(&g_deg[a.z], 1); atomicAdd(&g_deg[a.w], 1);
        atomicAdd(&g_deg[b.x], 1); atomicAdd(&g_deg[b.y], 1);
        atomicAdd(&g_deg[b.z], 1); atomicAdd(&g_deg[b.w], 1);
    } else {
        for (int e = e8; e < E; e++) atomicAdd(&g_deg[dstp[e]], 1);
    }
}

__global__ __launch_bounds__(256) void hist1_kernel(const int* __restrict__ dstp, int E) {
    int e = blockIdx.x * blockDim.x + threadIdx.x;
    if (e < E) atomicAdd(&g_deg[dstp[e]], 1);
}

// 3-phase scan: A = per-block scan + block totals, B = scan totals, C = add
__global__ __launch_bounds__(256) void scanA_kernel() {
    __shared__ int wsum[8];
    int t = threadIdx.x, lane = t & 31, w = t >> 5;
    int idx = blockIdx.x * 256 + t;
    int v = (idx < NN) ? g_deg[idx] : 0;
    int x = v;
    #pragma unroll
    for (int o = 1; o < 32; o <<= 1) {
        int tt = __shfl_up_sync(0xffffffffu, x, o);
        if (lane >= o) x += tt;
    }
    if (lane == 31) wsum[w] = x;
    __syncthreads();
    if (w == 0) {
        int s = (lane < 8) ? wsum[lane] : 0;
        #pragma unroll
        for (int o = 1; o < 8; o <<= 1) {
            int tt = __shfl_up_sync(0xffffffffu, s, o);
            if (lane >= o) s += tt;
        }
        if (lane < 8) wsum[lane] = s;
    }
    __syncthreads();
    int pre = (w > 0 ? wsum[w - 1] : 0) + (x - v);
    if (idx < NN) g_off[idx] = pre;
    if (t == 255) g_bsum[blockIdx.x] = pre + v;
}

__global__ __launch_bounds__(256) void scanB_kernel() {
    __shared__ int wsum[8];
    int t = threadIdx.x, lane = t & 31, w = t >> 5;
    int v = (t < NBLK) ? g_bsum[t] : 0;
    int x = v;
    #pragma unroll
    for (int o = 1; o < 32; o <<= 1) {
        int tt = __shfl_up_sync(0xffffffffu, x, o);
        if (lane >= o) x += tt;
    }
    if (lane == 31) wsum[w] = x;
    __syncthreads();
    if (w == 0) {
        int s = (lane < 8) ? wsum[lane] : 0;
        #pragma unroll
        for (int o = 1; o < 8; o <<= 1) {
            int tt = __shfl_up_sync(0xffffffffu, s, o);
            if (lane >= o) s += tt;
        }
        if (lane < 8) wsum[lane] = s;
    }
    __syncthreads();
    int pre = (w > 0 ? wsum[w - 1] : 0) + (x - v);
    if (t < NBLK) g_bsum[t] = pre;
}

__global__ __launch_bounds__(256) void scanC_kernel() {
    int idx = blockIdx.x * 256 + threadIdx.x;
    if (idx < NN) {
        int o = g_off[idx] + g_bsum[blockIdx.x];
        g_off[idx] = o;
        g_cur[idx] = o;
    }
}

__global__ __launch_bounds__(256) void scatter8_kernel(
    const int* __restrict__ srcp, const int* __restrict__ dstp, int E)
{
    int i = blockIdx.x * blockDim.x + threadIdx.x;
    int e8 = i * 8;
    if (e8 + 7 < E) {
        int4 sa = *(const int4*)(srcp + e8);
        int4 sb = *(const int4*)(srcp + e8 + 4);
        int4 da = *(const int4*)(dstp + e8);
        int4 db = *(const int4*)(dstp + e8 + 4);
        g_csr[atomicAdd(&g_cur[da.x], 1)] = sa.x;
        g_csr[atomicAdd(&g_cur[da.y], 1)] = sa.y;
        g_csr[atomicAdd(&g_cur[da.z], 1)] = sa.z;
        g_csr[atomicAdd(&g_cur[da.w], 1)] = sa.w;
        g_csr[atomicAdd(&g_cur[db.x], 1)] = sb.x;
        g_csr[atomicAdd(&g_cur[db.y], 1)] = sb.y;
        g_csr[atomicAdd(&g_cur[db.z], 1)] = sb.z;
        g_csr[atomicAdd(&g_cur[db.w], 1)] = sb.w;
    } else {
        for (int e = e8; e < E; e++)
            g_csr[atomicAdd(&g_cur[dstp[e]], 1)] = srcp[e];
    }
}

__global__ __launch_bounds__(256) void scatter1_kernel(
    const int* __restrict__ srcp, const int* __restrict__ dstp, int E)
{
    int e = blockIdx.x * blockDim.x + threadIdx.x;
    if (e < E) g_csr[atomicAdd(&g_cur[dstp[e]], 1)] = srcp[e];
}

__global__ __launch_bounds__(256) void self_scatter_kernel() {
    int i = blockIdx.x * blockDim.x + threadIdx.x;
    if (i < NN) g_csr[atomicAdd(&g_cur[i], 1)] = i;
}

// ---------------- per-node attention scalars --------------------------------
__global__ __launch_bounds__(256) void attn1_kernel(
    const float* __restrict__ att_src, const float* __restrict__ att_dst)
{
    int i = blockIdx.x * blockDim.x + threadIdx.x;   // n*HH + h
    if (i >= NN * HH) return;
    int n = i >> 2, h = i & 3;
    const float* xw = g_xw1 + (size_t)n * F1 + h * CC;
    float as = 0.f, ad = 0.f;
    #pragma unroll
    for (int c = 0; c < CC; c++) {
        float v = xw[c];
        as = fmaf(v, att_src[h * CC + c], as);
        ad = fmaf(v, att_dst[h * CC + c], ad);
    }
    g_asrc1[i] = as;
    g_adst1[i] = ad;
}

__global__ __launch_bounds__(256) void attn2_kernel(
    const float* __restrict__ att_src, const float* __restrict__ att_dst)
{
    int n = blockIdx.x * blockDim.x + threadIdx.x;
    if (n >= NN) return;
    const float* xw = g_xw2 + (size_t)n * F2;
    float as = 0.f, ad = 0.f;
    #pragma unroll
    for (int c = 0; c < F2; c++) {
        float v = xw[c];
        as = fmaf(v, att_src[c], as);
        ad = fmaf(v, att_dst[c], ad);
    }
    g_asrc2[n] = as;
    g_adst2[n] = ad;
}

// ---------------- layer 1 fused gather (half src) + bias + BN + ELU ---------
__global__ __launch_bounds__(256) void agg1_kernel(
    const float* __restrict__ b1,
    const float* __restrict__ gamma, const float* __restrict__ beta,
    const float* __restrict__ mean,  const float* __restrict__ var)
{
    int d = (blockIdx.x * blockDim.x + threadIdx.x) >> 5;
    int lane = threadIdx.x & 31;
    if (d >= NN) return;

    int start = g_off[d];
    int deg   = g_deg[d];
    int h = lane >> 3;
    float ad = g_adst1[d * 4 + h];

    float4 acc = make_float4(0.f, 0.f, 0.f, 0.f);
    float ssum = 0.f;

    for (int i = 0; i < deg; i += 32) {
        int remain = deg - i;
        int cnt = remain < 32 ? remain : 32;
        int sj = (lane < cnt) ? g_csr[start + i + lane] : 0;
        #pragma unroll 8
        for (int k = 0; k < cnt; k++) {
            int s = __shfl_sync(0xffffffffu, sj, k);
            float e = g_asrc1[s * 4 + h] + ad;
            float w = __expf(e > 0.f ? e : NEG * e);
            uint2 raw = *(const uint2*)(g_xw1h + (size_t)s * F1 + lane * 4);
            float2 f0 = __half22float2(*(__half2*)&raw.x);
            float2 f1 = __half22float2(*(__half2*)&raw.y);
            ssum += w;
            acc.x = fmaf(w, f0.x, acc.x);
            acc.y = fmaf(w, f0.y, acc.y);
            acc.z = fmaf(w, f1.x, acc.z);
            acc.w = fmaf(w, f1.y, acc.w);
        }
    }

    float inv = 1.f / (ssum + EPSV);
    int c0 = lane * 4;
    float o[4] = { acc.x * inv, acc.y * inv, acc.z * inv, acc.w * inv };
    #pragma unroll
    for (int j = 0; j < 4; j++) {
        int c = c0 + j;
        float hv = o[j] + b1[c];
        hv = (hv - mean[c]) * rsqrtf(var[c] + 1e-5f) * gamma[c] + beta[c];
        o[j] = hv > 0.f ? hv : expm1f(hv);
    }
    *(float4*)(g_h1 + (size_t)d * F1 + c0) = make_float4(o[0], o[1], o[2], o[3]);
}

// ---------------- layer 2 fused gather (half src) + bias -> out -------------
__global__ __launch_bounds__(256) void agg2_kernel(
    float* __restrict__ out, const float* __restrict__ b2)
{
    int d = (blockIdx.x * blockDim.x + threadIdx.x) >> 5;
    int lane = threadIdx.x & 31;
    if (d >= NN) return;

    int start = g_off[d];
    int deg   = g_deg[d];
    float ad = g_adst2[d];

    float2 acc = make_float2(0.f, 0.f);
    float ssum = 0.f;

    for (int i = 0; i < deg; i += 32) {
        int remain = deg - i;
        int cnt = remain < 32 ? remain : 32;
        int sj = (lane < cnt) ? g_csr[start + i + lane] : 0;
        #pragma unroll 8
        for (int k = 0; k < cnt; k++) {
            int s = __shfl_sync(0xffffffffu, sj, k);
            float e = g_asrc2[s] + ad;
            float w = __expf(e > 0.f ? e : NEG * e);
            unsigned raw = *(const unsigned*)(g_xw2h + (size_t)s * F2 + lane * 2);
            float2 f = __half22float2(*(__half2*)&raw);
            ssum += w;
            acc.x = fmaf(w, f.x, acc.x);
            acc.y = fmaf(w, f.y, acc.y);
        }
    }

    float inv = 1.f / (ssum + EPSV);
    int c0 = lane * 2;
    float2 ov;
    ov.x = acc.x * inv + b2[c0 + 0];
    ov.y = acc.y * inv + b2[c0 + 1];
    *(float2*)(out + (size_t)d * F2 + c0) = ov;
}

// ---------------- launch ----------------------------------------------------
extern "C" void kernel_launch(void* const* d_in, const int* in_sizes, int n_in,
                              void* d_out, int out_size)
{
    const float* x        = (const float*)d_in[0];
    const int*   ei       = (const int*)  d_in[1];
    const float* W1       = (const float*)d_in[2];
    const float* att_src1 = (const float*)d_in[3];
    const float* att_dst1 = (const float*)d_in[4];
    const float* b1       = (const float*)d_in[5];
    const float* bn_gamma = (const float*)d_in[6];
    const float* bn_beta  = (const float*)d_in[7];
    const float* bn_mean  = (const float*)d_in[8];
    const float* bn_var   = (const float*)d_in[9];
    const float* W2       = (const float*)d_in[10];
    const float* att_src2 = (const float*)d_in[11];
    const float* att_dst2 = (const float*)d_in[12];
    const float* b2       = (const float*)d_in[13];
    float* out = (float*)d_out;

    int E  = in_sizes[1] / 2;
    const int* srcp = ei;
    const int* dstp = ei + E;

    float  *p_xw1 = nullptr, *p_h1 = nullptr, *p_xw2 = nullptr;
    __half *p_xw1h = nullptr, *p_xw2h = nullptr;
    cudaGetSymbolAddress((void**)&p_xw1,  g_xw1);
    cudaGetSymbolAddress((void**)&p_xw1h, g_xw1h);
    cudaGetSymbolAddress((void**)&p_h1,   g_h1);
    cudaGetSymbolAddress((void**)&p_xw2,  g_xw2);
    cudaGetSymbolAddress((void**)&p_xw2h, g_xw2h);

    static cudaStream_t s_side = nullptr;
    static cudaEvent_t ev_fork = nullptr, ev_join = nullptr;
    if (!s_side) {
        cudaStreamCreateWithFlags(&s_side, cudaStreamNonBlocking);
        cudaEventCreateWithFlags(&ev_fork, cudaEventDisableTiming);
        cudaEventCreateWithFlags(&ev_join, cudaEventDisableTiming);
    }

    bool vec_ok = (E % 4 == 0) &&
                  ((((uintptr_t)srcp) & 15u) == 0) &&
                  ((((uintptr_t)dstp) & 15u) == 0);

    // ---- fork: CSR build on side stream, GEMM1+attn1 on main ----------------
    cudaEventRecord(ev_fork, 0);
    cudaStreamWaitEvent(s_side, ev_fork, 0);

    init_deg_kernel<<<(NN + 255) / 256, 256, 0, s_side>>>();
    if (vec_ok) {
        hist8_kernel<<<((E + 7) / 8 + 255) / 256, 256, 0, s_side>>>(dstp, E);
    } else {
        hist1_kernel<<<(E + 255) / 256, 256, 0, s_side>>>(dstp, E);
    }
    scanA_kernel<<<NBLK, 256, 0, s_side>>>();
    scanB_kernel<<<1, 256, 0, s_side>>>();
    scanC_kernel<<<NBLK, 256, 0, s_side>>>();
    if (vec_ok) {
        scatter8_kernel<<<((E + 7) / 8 + 255) / 256, 256, 0, s_side>>>(srcp, dstp, E);
    } else {
        scatter1_kernel<<<(E + 255) / 256, 256, 0, s_side>>>(srcp, dstp, E);
    }
    self_scatter_kernel<<<(NN + 255) / 256, 256, 0, s_side>>>();

    {
        dim3 grid(1, (NN + 127) / 128);
        gemm_tc<F1, 256><<<grid, 256>>>(x, W1, p_xw1, p_xw1h, NN);
    }
    attn1_kernel<<<(NN * HH + 255) / 256, 256>>>(att_src1, att_dst1);

    // ---- join ----------------------------------------------------------------
    cudaEventRecord(ev_join, s_side);
    cudaStreamWaitEvent(0, ev_join, 0);

    // ---- layer 1 aggregate + layer 2 -----------------------------------------
    agg1_kernel<<<(NN * 32 + 255) / 256, 256>>>(b1, bn_gamma, bn_beta, bn_mean, bn_var);
    {
        dim3 grid(1, (NN + 127) / 128);
        gemm_tc<F2, 128><<<grid, 128>>>(p_h1, W2, p_xw2, p_xw2h, NN);
    }
    attn2_kernel<<<(NN + 255) / 256, 256>>>(att_src2, att_dst2);
    agg2_kernel<<<(NN * 32 + 255) / 256, 256>>>(out, b2);
}

// round 6
// speedup vs baseline: 2.9277x; 1.2732x over previous
#include <cuda_runtime.h>
#include <cuda_fp16.h>
#include <math.h>
#include <stdint.h>

#define NN 50000
#define HH 4
#define CC 32
#define F1 128
#define F2 64
#define NEG 0.2f
#define EPSV 1e-16f
#define EMAX 1600000   // real edges only (self loops handled analytically)
#define NBLK ((NN + 255) / 256)

// ---------------- scratch (device globals; no allocations allowed) ----------
__device__ __align__(16) __half g_xw1h[NN * F1];  // x@W1 half (agg1 gather)
__device__ float  g_h1 [NN * F1];                 // layer1 output (gemm2 input)
__device__ float  g_asrc1[NN * HH];
__device__ float  g_adst1[NN * HH];
__device__ __align__(16) __half g_xw2h[NN * F2];  // h@W2 half (agg2 gather)
__device__ float  g_asrc2[NN];
__device__ float  g_adst2[NN];
__device__ int    g_deg[NN];          // ZERO before each use; scanA re-zeroes
__device__ int    g_off[NN];          // CSR segment start
__device__ int    g_cur[NN];          // scatter cursor
__device__ int    g_bsum[256];        // block sums for scan
__device__ int    g_csr[EMAX];        // src node per edge, grouped by dst

// ---------------- GEMM1: xw1h = half(x @ W1), fused attn1 -------------------
// BM=128, BN=128, BK=8, NT=256, 8x8 microtile. Epilogue: per-head dot with
// att_src1/att_dst1 (4 heads x 32) reduced via shfl across 4 threads.
__global__ __launch_bounds__(256) void gemm1_kernel(
    const float* __restrict__ A, const float* __restrict__ B,
    __half* __restrict__ Ch,
    const float* __restrict__ att_src, const float* __restrict__ att_dst, int M)
{
    const int BM = 128, BN = 128, BK = 8, KTOT = 128, NT = 256, TX = 16;
    __shared__ float As[2][BK * BM];
    __shared__ float Bs[2][BK * BN];

    int tid = threadIdx.x;
    int tx = tid % TX;
    int ty = tid / TX;
    int row0 = blockIdx.y * BM;

    float acc[8][8] = {};

    auto load_tile = [&](int buf, int kt) {
        int k0 = kt * BK;
        #pragma unroll
        for (int idx = tid; idx < BM * BK / 4; idx += NT) {
            int row = idx >> 1;
            int kc  = (idx & 1) * 4;
            int gr = row0 + row;
            float4 v = make_float4(0.f, 0.f, 0.f, 0.f);
            if (gr < M) v = *(const float4*)(A + (size_t)gr * KTOT + k0 + kc);
            As[buf][(kc + 0) * BM + row] = v.x;
            As[buf][(kc + 1) * BM + row] = v.y;
            As[buf][(kc + 2) * BM + row] = v.z;
            As[buf][(kc + 3) * BM + row] = v.w;
        }
        #pragma unroll
        for (int idx = tid; idx < BK * BN / 4; idx += NT) {
            int r  = idx / (BN / 4);
            int c4 = (idx % (BN / 4)) * 4;
            *(float4*)&Bs[buf][r * BN + c4] =
                *(const float4*)(B + (size_t)(k0 + r) * BN + c4);
        }
    };

    load_tile(0, 0);
    __syncthreads();

    int buf = 0;
    for (int kt = 0; kt < KTOT / BK; kt++) {
        if (kt + 1 < KTOT / BK) load_tile(buf ^ 1, kt + 1);
        #pragma unroll
        for (int kk = 0; kk < BK; kk++) {
            float4 a0 = *(const float4*)&As[buf][kk * BM + ty * 8];
            float4 a1 = *(const float4*)&As[buf][kk * BM + ty * 8 + 4];
            float4 b0 = *(const float4*)&Bs[buf][kk * BN + tx * 8];
            float4 b1 = *(const float4*)&Bs[buf][kk * BN + tx * 8 + 4];
            float av[8] = {a0.x,a0.y,a0.z,a0.w,a1.x,a1.y,a1.z,a1.w};
            float bv[8] = {b0.x,b0.y,b0.z,b0.w,b1.x,b1.y,b1.z,b1.w};
            #pragma unroll
            for (int i = 0; i < 8; i++)
                #pragma unroll
                for (int j = 0; j < 8; j++)
                    acc[i][j] = fmaf(av[i], bv[j], acc[i][j]);
        }
        __syncthreads();
        buf ^= 1;
    }

    // att weights for this thread's 8 columns (flattened [4,32] layout)
    float as1[8], ad1[8];
    #pragma unroll
    for (int j = 0; j < 8; j++) {
        as1[j] = att_src[tx * 8 + j];
        ad1[j] = att_dst[tx * 8 + j];
    }
    int h = tx >> 2;

    #pragma unroll
    for (int i = 0; i < 8; i++) {
        int gr = row0 + ty * 8 + i;
        float ps = 0.f, pd = 0.f;
        #pragma unroll
        for (int j = 0; j < 8; j++) {
            ps = fmaf(acc[i][j], as1[j], ps);
            pd = fmaf(acc[i][j], ad1[j], pd);
        }
        ps += __shfl_xor_sync(0xffffffffu, ps, 1);
        pd += __shfl_xor_sync(0xffffffffu, pd, 1);
        ps += __shfl_xor_sync(0xffffffffu, ps, 2);
        pd += __shfl_xor_sync(0xffffffffu, pd, 2);
        if (gr < M) {
            __half2 p0 = __floats2half2_rn(acc[i][0], acc[i][1]);
            __half2 p1 = __floats2half2_rn(acc[i][2], acc[i][3]);
            __half2 p2 = __floats2half2_rn(acc[i][4], acc[i][5]);
            __half2 p3 = __floats2half2_rn(acc[i][6], acc[i][7]);
            uint4 u = make_uint4(*(unsigned*)&p0, *(unsigned*)&p1,
                                 *(unsigned*)&p2, *(unsigned*)&p3);
            *(uint4*)(Ch + (size_t)gr * BN + tx * 8) = u;
            if ((tx & 3) == 0) {
                g_asrc1[gr * 4 + h] = ps;
                g_adst1[gr * 4 + h] = pd;
            }
        }
    }
}

// ---------------- GEMM2: xw2h = half(h1 @ W2), fused attn2 (1 head x 64) ----
__global__ __launch_bounds__(128) void gemm2_kernel(
    const float* __restrict__ A, const float* __restrict__ B,
    __half* __restrict__ Ch,
    const float* __restrict__ att_src, const float* __restrict__ att_dst, int M)
{
    const int BM = 128, BN = 64, BK = 8, KTOT = 128, NT = 128, TX = 8;
    __shared__ float As[2][BK * BM];
    __shared__ float Bs[2][BK * BN];

    int tid = threadIdx.x;
    int tx = tid % TX;
    int ty = tid / TX;
    int row0 = blockIdx.y * BM;

    float acc[8][8] = {};

    auto load_tile = [&](int buf, int kt) {
        int k0 = kt * BK;
        #pragma unroll
        for (int idx = tid; idx < BM * BK / 4; idx += NT) {
            int row = idx >> 1;
            int kc  = (idx & 1) * 4;
            int gr = row0 + row;
            float4 v = make_float4(0.f, 0.f, 0.f, 0.f);
            if (gr < M) v = *(const float4*)(A + (size_t)gr * KTOT + k0 + kc);
            As[buf][(kc + 0) * BM + row] = v.x;
            As[buf][(kc + 1) * BM + row] = v.y;
            As[buf][(kc + 2) * BM + row] = v.z;
            As[buf][(kc + 3) * BM + row] = v.w;
        }
        #pragma unroll
        for (int idx = tid; idx < BK * BN / 4; idx += NT) {
            int r  = idx / (BN / 4);
            int c4 = (idx % (BN / 4)) * 4;
            *(float4*)&Bs[buf][r * BN + c4] =
                *(const float4*)(B + (size_t)(k0 + r) * BN + c4);
        }
    };

    load_tile(0, 0);
    __syncthreads();

    int buf = 0;
    for (int kt = 0; kt < KTOT / BK; kt++) {
        if (kt + 1 < KTOT / BK) load_tile(buf ^ 1, kt + 1);
        #pragma unroll
        for (int kk = 0; kk < BK; kk++) {
            float4 a0 = *(const float4*)&As[buf][kk * BM + ty * 8];
            float4 a1 = *(const float4*)&As[buf][kk * BM + ty * 8 + 4];
            float4 b0 = *(const float4*)&Bs[buf][kk * BN + tx * 8];
            float4 b1 = *(const float4*)&Bs[buf][kk * BN + tx * 8 + 4];
            float av[8] = {a0.x,a0.y,a0.z,a0.w,a1.x,a1.y,a1.z,a1.w};
            float bv[8] = {b0.x,b0.y,b0.z,b0.w,b1.x,b1.y,b1.z,b1.w};
            #pragma unroll
            for (int i = 0; i < 8; i++)
                #pragma unroll
                for (int j = 0; j < 8; j++)
                    acc[i][j] = fmaf(av[i], bv[j], acc[i][j]);
        }
        __syncthreads();
        buf ^= 1;
    }

    float as2[8], ad2[8];
    #pragma unroll
    for (int j = 0; j < 8; j++) {
        as2[j] = att_src[tx * 8 + j];
        ad2[j] = att_dst[tx * 8 + j];
    }

    #pragma unroll
    for (int i = 0; i < 8; i++) {
        int gr = row0 + ty * 8 + i;
        float ps = 0.f, pd = 0.f;
        #pragma unroll
        for (int j = 0; j < 8; j++) {
            ps = fmaf(acc[i][j], as2[j], ps);
            pd = fmaf(acc[i][j], ad2[j], pd);
        }
        ps += __shfl_xor_sync(0xffffffffu, ps, 1);
        pd += __shfl_xor_sync(0xffffffffu, pd, 1);
        ps += __shfl_xor_sync(0xffffffffu, ps, 2);
        pd += __shfl_xor_sync(0xffffffffu, pd, 2);
        ps += __shfl_xor_sync(0xffffffffu, ps, 4);
        pd += __shfl_xor_sync(0xffffffffu, pd, 4);
        if (gr < M) {
            __half2 p0 = __floats2half2_rn(acc[i][0], acc[i][1]);
            __half2 p1 = __floats2half2_rn(acc[i][2], acc[i][3]);
            __half2 p2 = __floats2half2_rn(acc[i][4], acc[i][5]);
            __half2 p3 = __floats2half2_rn(acc[i][6], acc[i][7]);
            uint4 u = make_uint4(*(unsigned*)&p0, *(unsigned*)&p1,
                                 *(unsigned*)&p2, *(unsigned*)&p3);
            *(uint4*)(Ch + (size_t)gr * BN + tx * 8) = u;
            if (tx == 0) {
                g_asrc2[gr] = ps;
                g_adst2[gr] = pd;
            }
        }
    }
}

// ---------------- CSR build (real edges only) -------------------------------
__global__ __launch_bounds__(256) void hist8_kernel(const int* __restrict__ dstp, int E) {
    int i = blockIdx.x * blockDim.x + threadIdx.x;
    int e8 = i * 8;
    if (e8 + 7 < E) {
        int4 a = *(const int4*)(dstp + e8);
        int4 b = *(const int4*)(dstp + e8 + 4);
        atomicAdd(&g_deg[a.x], 1); atomicAdd(&g_deg[a.y], 1);
        atomicAdd(&g_deg[a.z], 1); atomicAdd(&g_deg[a.w], 1);
        atomicAdd(&g_deg[b.x], 1); atomicAdd(&g_deg[b.y], 1);
        atomicAdd(&g_deg[b.z], 1); atomicAdd(&g_deg[b.w], 1);
    } else {
        for (int e = e8; e < E; e++) atomicAdd(&g_deg[dstp[e]], 1);
    }
}

__global__ __launch_bounds__(256) void hist1_kernel(const int* __restrict__ dstp, int E) {
    int e = blockIdx.x * blockDim.x + threadIdx.x;
    if (e < E) atomicAdd(&g_deg[dstp[e]], 1);
}

// per-block exclusive scan of g_deg -> g_off(local), g_bsum; zeroes g_deg
__global__ __launch_bounds__(256) void scanA_kernel() {
    __shared__ int wsum[8];
    int t = threadIdx.x, lane = t & 31, w = t >> 5;
    int idx = blockIdx.x * 256 + t;
    int v = (idx < NN) ? g_deg[idx] : 0;
    int x = v;
    #pragma unroll
    for (int o = 1; o < 32; o <<= 1) {
        int tt = __shfl_up_sync(0xffffffffu, x, o);
        if (lane >= o) x += tt;
    }
    if (lane == 31) wsum[w] = x;
    __syncthreads();
    if (w == 0) {
        int s = (lane < 8) ? wsum[lane] : 0;
        #pragma unroll
        for (int o = 1; o < 8; o <<= 1) {
            int tt = __shfl_up_sync(0xffffffffu, s, o);
            if (lane >= o) s += tt;
        }
        if (lane < 8) wsum[lane] = s;
    }
    __syncthreads();
    int pre = (w > 0 ? wsum[w - 1] : 0) + (x - v);
    if (idx < NN) {
        g_off[idx] = pre;
        g_deg[idx] = 0;               // self-clean for next invocation
    }
    if (t == 255) g_bsum[blockIdx.x] = pre + v;
}

// add block offset (reduce prefix of g_bsum inline), init cursors
__global__ __launch_bounds__(256) void scanC_kernel() {
    __shared__ int wsum[8];
    __shared__ int s_total;
    int t = threadIdx.x, lane = t & 31, w = t >> 5;
    int v = (t < (int)blockIdx.x && t < NBLK) ? g_bsum[t] : 0;
    #pragma unroll
    for (int o = 16; o > 0; o >>= 1) v += __shfl_xor_sync(0xffffffffu, v, o);
    if (lane == 0) wsum[w] = v;
    __syncthreads();
    if (t == 0) {
        int s = 0;
        #pragma unroll
        for (int k = 0; k < 8; k++) s += wsum[k];
        s_total = s;
    }
    __syncthreads();
    int idx = blockIdx.x * 256 + t;
    if (idx < NN) {
        int o = g_off[idx] + s_total;
        g_off[idx] = o;
        g_cur[idx] = o;
    }
}

__global__ __launch_bounds__(256) void scatter8_kernel(
    const int* __restrict__ srcp, const int* __restrict__ dstp, int E)
{
    int i = blockIdx.x * blockDim.x + threadIdx.x;
    int e8 = i * 8;
    if (e8 + 7 < E) {
        int4 sa = *(const int4*)(srcp + e8);
        int4 sb = *(const int4*)(srcp + e8 + 4);
        int4 da = *(const int4*)(dstp + e8);
        int4 db = *(const int4*)(dstp + e8 + 4);
        g_csr[atomicAdd(&g_cur[da.x], 1)] = sa.x;
        g_csr[atomicAdd(&g_cur[da.y], 1)] = sa.y;
        g_csr[atomicAdd(&g_cur[da.z], 1)] = sa.z;
        g_csr[atomicAdd(&g_cur[da.w], 1)] = sa.w;
        g_csr[atomicAdd(&g_cur[db.x], 1)] = sb.x;
        g_csr[atomicAdd(&g_cur[db.y], 1)] = sb.y;
        g_csr[atomicAdd(&g_cur[db.z], 1)] = sb.z;
        g_csr[atomicAdd(&g_cur[db.w], 1)] = sb.w;
    } else {
        for (int e = e8; e < E; e++)
            g_csr[atomicAdd(&g_cur[dstp[e]], 1)] = srcp[e];
    }
}

__global__ __launch_bounds__(256) void scatter1_kernel(
    const int* __restrict__ srcp, const int* __restrict__ dstp, int E)
{
    int e = blockIdx.x * blockDim.x + threadIdx.x;
    if (e < E) g_csr[atomicAdd(&g_cur[dstp[e]], 1)] = srcp[e];
}

// ---------------- layer 1 fused gather + self-loop + bias + BN + ELU --------
__global__ __launch_bounds__(256) void agg1_kernel(
    const float* __restrict__ b1,
    const float* __restrict__ gamma, const float* __restrict__ beta,
    const float* __restrict__ mean,  const float* __restrict__ var, int E)
{
    int d = (blockIdx.x * blockDim.x + threadIdx.x) >> 5;
    int lane = threadIdx.x & 31;
    if (d >= NN) return;

    int start = g_off[d];
    int end   = (d + 1 < NN) ? g_off[d + 1] : E;
    int h = lane >> 3;
    float ad = g_adst1[d * 4 + h];

    // self-loop term
    float e0 = g_asrc1[d * 4 + h] + ad;
    float ssum = __expf(e0 > 0.f ? e0 : NEG * e0);
    float4 acc;
    {
        uint2 raw = *(const uint2*)(g_xw1h + (size_t)d * F1 + lane * 4);
        float2 f0 = __half22float2(*(__half2*)&raw.x);
        float2 f1 = __half22float2(*(__half2*)&raw.y);
        acc = make_float4(ssum * f0.x, ssum * f0.y, ssum * f1.x, ssum * f1.y);
    }

    for (int i = start; i < end; i += 32) {
        int cnt = min(end - i, 32);
        int sj = (lane < cnt) ? g_csr[i + lane] : 0;
        #pragma unroll 8
        for (int k = 0; k < cnt; k++) {
            int s = __shfl_sync(0xffffffffu, sj, k);
            float e = g_asrc1[s * 4 + h] + ad;
            float w = __expf(e > 0.f ? e : NEG * e);
            uint2 raw = *(const uint2*)(g_xw1h + (size_t)s * F1 + lane * 4);
            float2 f0 = __half22float2(*(__half2*)&raw.x);
            float2 f1 = __half22float2(*(__half2*)&raw.y);
            ssum += w;
            acc.x = fmaf(w, f0.x, acc.x);
            acc.y = fmaf(w, f0.y, acc.y);
            acc.z = fmaf(w, f1.x, acc.z);
            acc.w = fmaf(w, f1.y, acc.w);
        }
    }

    float inv = 1.f / (ssum + EPSV);
    int c0 = lane * 4;
    float o[4] = { acc.x * inv, acc.y * inv, acc.z * inv, acc.w * inv };
    #pragma unroll
    for (int j = 0; j < 4; j++) {
        int c = c0 + j;
        float hv = o[j] + b1[c];
        hv = (hv - mean[c]) * rsqrtf(var[c] + 1e-5f) * gamma[c] + beta[c];
        o[j] = hv > 0.f ? hv : expm1f(hv);
    }
    *(float4*)(g_h1 + (size_t)d * F1 + c0) = make_float4(o[0], o[1], o[2], o[3]);
}

// ---------------- layer 2 fused gather + self-loop + bias -> out ------------
__global__ __launch_bounds__(256) void agg2_kernel(
    float* __restrict__ out, const float* __restrict__ b2, int E)
{
    int d = (blockIdx.x * blockDim.x + threadIdx.x) >> 5;
    int lane = threadIdx.x & 31;
    if (d >= NN) return;

    int start = g_off[d];
    int end   = (d + 1 < NN) ? g_off[d + 1] : E;
    float ad = g_adst2[d];

    float e0 = g_asrc2[d] + ad;
    float ssum = __expf(e0 > 0.f ? e0 : NEG * e0);
    float2 acc;
    {
        unsigned raw = *(const unsigned*)(g_xw2h + (size_t)d * F2 + lane * 2);
        float2 f = __half22float2(*(__half2*)&raw);
        acc = make_float2(ssum * f.x, ssum * f.y);
    }

    for (int i = start; i < end; i += 32) {
        int cnt = min(end - i, 32);
        int sj = (lane < cnt) ? g_csr[i + lane] : 0;
        #pragma unroll 8
        for (int k = 0; k < cnt; k++) {
            int s = __shfl_sync(0xffffffffu, sj, k);
            float e = g_asrc2[s] + ad;
            float w = __expf(e > 0.f ? e : NEG * e);
            unsigned raw = *(const unsigned*)(g_xw2h + (size_t)s * F2 + lane * 2);
            float2 f = __half22float2(*(__half2*)&raw);
            ssum += w;
            acc.x = fmaf(w, f.x, acc.x);
            acc.y = fmaf(w, f.y, acc.y);
        }
    }

    float inv = 1.f / (ssum + EPSV);
    int c0 = lane * 2;
    float2 ov;
    ov.x = acc.x * inv + b2[c0 + 0];
    ov.y = acc.y * inv + b2[c0 + 1];
    *(float2*)(out + (size_t)d * F2 + c0) = ov;
}

// ---------------- launch ----------------------------------------------------
extern "C" void kernel_launch(void* const* d_in, const int* in_sizes, int n_in,
                              void* d_out, int out_size)
{
    const float* x        = (const float*)d_in[0];
    const int*   ei       = (const int*)  d_in[1];
    const float* W1       = (const float*)d_in[2];
    const float* att_src1 = (const float*)d_in[3];
    const float* att_dst1 = (const float*)d_in[4];
    const float* b1       = (const float*)d_in[5];
    const float* bn_gamma = (const float*)d_in[6];
    const float* bn_beta  = (const float*)d_in[7];
    const float* bn_mean  = (const float*)d_in[8];
    const float* bn_var   = (const float*)d_in[9];
    const float* W2       = (const float*)d_in[10];
    const float* att_src2 = (const float*)d_in[11];
    const float* att_dst2 = (const float*)d_in[12];
    const float* b2       = (const float*)d_in[13];
    float* out = (float*)d_out;

    int E  = in_sizes[1] / 2;
    const int* srcp = ei;
    const int* dstp = ei + E;

    float  *p_h1 = nullptr;
    __half *p_xw1h = nullptr, *p_xw2h = nullptr;
    cudaGetSymbolAddress((void**)&p_xw1h, g_xw1h);
    cudaGetSymbolAddress((void**)&p_h1,   g_h1);
    cudaGetSymbolAddress((void**)&p_xw2h, g_xw2h);

    static cudaStream_t s_side = nullptr;
    static cudaEvent_t ev_fork = nullptr, ev_join = nullptr;
    if (!s_side) {
        cudaStreamCreateWithFlags(&s_side, cudaStreamNonBlocking);
        cudaEventCreateWithFlags(&ev_fork, cudaEventDisableTiming);
        cudaEventCreateWithFlags(&ev_join, cudaEventDisableTiming);
    }

    bool vec_ok = (E % 4 == 0) &&
                  ((((uintptr_t)srcp) & 15u) == 0) &&
                  ((((uintptr_t)dstp) & 15u) == 0);

    // ---- fork: CSR build on side stream, GEMM1(+attn1) on main --------------
    cudaEventRecord(ev_fork, 0);
    cudaStreamWaitEvent(s_side, ev_fork, 0);

    if (vec_ok) {
        hist8_kernel<<<((E + 7) / 8 + 255) / 256, 256, 0, s_side>>>(dstp, E);
    } else {
        hist1_kernel<<<(E + 255) / 256, 256, 0, s_side>>>(dstp, E);
    }
    scanA_kernel<<<NBLK, 256, 0, s_side>>>();
    scanC_kernel<<<NBLK, 256, 0, s_side>>>();
    if (vec_ok) {
        scatter8_kernel<<<((E + 7) / 8 + 255) / 256, 256, 0, s_side>>>(srcp, dstp, E);
    } else {
        scatter1_kernel<<<(E + 255) / 256, 256, 0, s_side>>>(srcp, dstp, E);
    }

    {
        dim3 grid(1, (NN + 127) / 128);
        gemm1_kernel<<<grid, 256>>>(x, W1, p_xw1h, att_src1, att_dst1, NN);
    }

    // ---- join ----------------------------------------------------------------
    cudaEventRecord(ev_join, s_side);
    cudaStreamWaitEvent(0, ev_join, 0);

    // ---- layer 1 aggregate + layer 2 ------------------------------------------
    agg1_kernel<<<(NN * 32 + 255) / 256, 256>>>(b1, bn_gamma, bn_beta, bn_mean, bn_var, E);
    {
        dim3 grid(1, (NN + 127) / 128);
        gemm2_kernel<<<grid, 128>>>(p_h1, W2, p_xw2h, att_src2, att_dst2, NN);
    }
    agg2_kernel<<<(NN * 32 + 255) / 256, 256>>>(out, b2, E);
}